// round 1
// baseline (speedup 1.0000x reference)
#include <cuda_runtime.h>

// Inputs (metadata order, matching reference setup_inputs):
// 0: user_id  int32 [16384]
// 1: item_id  int32 [16384]
// 2: category int32 [16384]
// 3: emb_user f32   [100000]   (D_USER x 1)
// 4: emb_item f32   [50000]
// 5: emb_cat  f32   [1000]
// 6: cross_w  f32   [150000000]
// out: f32 [16384]  (B x 1)

#define D_USER  100000
#define D_ITEM  50000
#define D_CAT   1000
#define OFF_IC  (D_USER * D_CAT)   // 100,000,000

__global__ void wide_kernel(const int* __restrict__ user_id,
                            const int* __restrict__ item_id,
                            const int* __restrict__ category,
                            const float* __restrict__ emb_user,
                            const float* __restrict__ emb_item,
                            const float* __restrict__ emb_cat,
                            const float* __restrict__ cross_w,
                            float* __restrict__ out,
                            int n)
{
    int i = blockIdx.x * blockDim.x + threadIdx.x;
    if (i >= n) return;

    int u = user_id[i];
    int it = item_id[i];
    int c = category[i];

    // Issue the two long-latency cross_w gathers first to maximize MLP.
    int idx_uc = u * D_CAT + c;                    // < 100M, fits int32
    int idx_ic = OFF_IC + it * D_CAT + c;          // < 150M, fits int32
    float cw0 = __ldg(&cross_w[idx_uc]);
    float cw1 = __ldg(&cross_w[idx_ic]);

    float wide = __ldg(&emb_user[u]) + __ldg(&emb_item[it]) + __ldg(&emb_cat[c]);

    out[i] = wide + cw0 + cw1;
}

extern "C" void kernel_launch(void* const* d_in, const int* in_sizes, int n_in,
                              void* d_out, int out_size)
{
    const int*   user_id  = (const int*)d_in[0];
    const int*   item_id  = (const int*)d_in[1];
    const int*   category = (const int*)d_in[2];
    const float* emb_user = (const float*)d_in[3];
    const float* emb_item = (const float*)d_in[4];
    const float* emb_cat  = (const float*)d_in[5];
    const float* cross_w  = (const float*)d_in[6];
    float* out = (float*)d_out;

    int n = in_sizes[0];  // B = 16384
    int threads = 256;
    int blocks = (n + threads - 1) / threads;
    wide_kernel<<<blocks, threads>>>(user_id, item_id, category,
                                     emb_user, emb_item, emb_cat, cross_w,
                                     out, n);
}